// round 1
// baseline (speedup 1.0000x reference)
#include <cuda_runtime.h>
#include <cuda_bf16.h>
#include <math.h>

#define BATCH   128
#define OUT_DIM 1024
#define IN_DIM  2048
#define MAXNNZ  64          // Poisson(8): P(row nnz > 64) ~ 1e-40 — safe cap

// Scratch: CSR-with-cap connectivity table (no allocations allowed in kernel_launch)
__device__ int            g_cnt[OUT_DIM];
__device__ unsigned short g_idx[OUT_DIM][MAXNNZ];

// ---------------------------------------------------------------------------
// Kernel 1: one warp per check-node row. Scan 2048 mask floats, compact the
// nonzero column indices deterministically (ballot + prefix popc, no atomics).
// 4x float4 loads in flight per iteration for memory-level parallelism.
// ---------------------------------------------------------------------------
__global__ void build_row_indices(const float* __restrict__ mask) {
    int warp = (blockIdx.x * blockDim.x + threadIdx.x) >> 5;
    int lane = threadIdx.x & 31;
    if (warp >= OUT_DIM) return;

    const float* row = mask + (size_t)warp * IN_DIM;
    int cnt = 0;

    // 2048 floats = 4 iterations x 512 floats (4 float4 per lane per iteration)
    #pragma unroll 1
    for (int c = 0; c < IN_DIM; c += 512) {
        float4 v[4];
        #pragma unroll
        for (int u = 0; u < 4; u++)
            v[u] = reinterpret_cast<const float4*>(row + c + u * 128)[lane];

        #pragma unroll
        for (int u = 0; u < 4; u++) {
            float m[4] = {v[u].x, v[u].y, v[u].z, v[u].w};
            #pragma unroll
            for (int k = 0; k < 4; k++) {
                unsigned bal = __ballot_sync(0xffffffffu, m[k] != 0.0f);
                if (m[k] != 0.0f) {
                    int pos = cnt + __popc(bal & ((1u << lane) - 1u));
                    if (pos < MAXNNZ)
                        g_idx[warp][pos] =
                            (unsigned short)(c + u * 128 + lane * 4 + k);
                }
                cnt += __popc(bal);
            }
        }
    }
    if (lane == 0) g_cnt[warp] = cnt < MAXNNZ ? cnt : MAXNNZ;
}

// ---------------------------------------------------------------------------
// Kernel 2: block = 32 check nodes (threadIdx.x, coalesced output) x 8 batches
// (threadIdx.y). Index lists staged in shared (padded stride: no bank
// conflicts). Each thread gathers ~8 x values (L1-resident 8KB x-row) and
// computes 2*atanh(clip(prod)).
// ---------------------------------------------------------------------------
__global__ void __launch_bounds__(256)
check_node_update(const float* __restrict__ x, float* __restrict__ out) {
    __shared__ unsigned short s_idx[32][MAXNNZ + 2];  // +2 shorts: kill bank conflicts
    __shared__ int            s_cnt[32];

    const int o_base = blockIdx.x * 32;
    const int tx  = threadIdx.x;               // 0..31 -> o
    const int ty  = threadIdx.y;               // 0..7  -> b
    const int tid = ty * 32 + tx;

    // Cooperative load of 32 index rows into shared
    #pragma unroll
    for (int t = tid; t < 32 * MAXNNZ; t += 256) {
        int r = t >> 6;           // / MAXNNZ
        int j = t & (MAXNNZ - 1); // % MAXNNZ
        s_idx[r][j] = g_idx[o_base + r][j];
    }
    if (tid < 32) s_cnt[tid] = g_cnt[o_base + tid];
    __syncthreads();

    const int o = o_base + tx;
    const int b = blockIdx.y * 8 + ty;
    const float* __restrict__ xrow = x + (size_t)b * IN_DIM;

    const int n = s_cnt[tx];
    const unsigned short* ids = s_idx[tx];

    float p = 1.0f;
    int j = 0;
    #pragma unroll 1
    for (; j + 4 <= n; j += 4) {     // independent loads -> MLP
        float a0 = xrow[ids[j + 0]];
        float a1 = xrow[ids[j + 1]];
        float a2 = xrow[ids[j + 2]];
        float a3 = xrow[ids[j + 3]];
        p *= (a0 * a1) * (a2 * a3);
    }
    for (; j < n; j++) p *= xrow[ids[j]];

    const float lim = 1.0f - 1e-7f;  // folds to 0.99999988f, same as reference
    p = fminf(fmaxf(p, -lim), lim);

    out[(size_t)b * OUT_DIM + o] = logf((1.0f + p) / (1.0f - p));
}

// ---------------------------------------------------------------------------
extern "C" void kernel_launch(void* const* d_in, const int* in_sizes, int n_in,
                              void* d_out, int out_size) {
    const float* x    = (const float*)d_in[0];   // [128, 2048]
    const float* mask = (const float*)d_in[1];   // [1024, 2048]
    float*       out  = (float*)d_out;           // [128, 1024]

    // 1024 rows, one warp each: 128 blocks x 256 threads (8 warps)
    build_row_indices<<<128, 256>>>(mask);

    dim3 blk(32, 8);
    dim3 grd(OUT_DIM / 32, BATCH / 8);  // (32, 16)
    check_node_update<<<grd, blk>>>(x, out);
}

// round 2
// speedup vs baseline: 1.4018x; 1.4018x over previous
#include <cuda_runtime.h>
#include <cuda_bf16.h>
#include <math.h>

#define BATCH   128
#define OUT_DIM 1024
#define IN_DIM  2048
#define MAXNNZ  64          // Poisson(8): P(row nnz > 64) ~ 1e-40 — safe cap

// Scratch (no allocations allowed): transposed CSR-with-cap connectivity.
// g_idxT[j][o] = column index of j-th nonzero of mask row o. Transposed so a
// warp of consecutive-o lanes reads index j in ONE coalesced 64B load.
__device__ int            g_cnt[OUT_DIM];
__device__ unsigned short g_idxT[MAXNNZ][OUT_DIM];

// ---------------------------------------------------------------------------
// Kernel 1: one warp per mask row. 8 float4 loads in flight per lane (4KB per
// warp) for DRAM MLP; ballot+prefix-popc compaction (deterministic, no
// atomics); scattered ushort writes into the transposed table (~8 per row).
// ---------------------------------------------------------------------------
__global__ void build_row_indices(const float* __restrict__ mask) {
    int warp = (blockIdx.x * blockDim.x + threadIdx.x) >> 5;
    int lane = threadIdx.x & 31;
    if (warp >= OUT_DIM) return;

    const float* row = mask + (size_t)warp * IN_DIM;
    int cnt = 0;

    #pragma unroll
    for (int c = 0; c < IN_DIM; c += 1024) {   // 2 iterations
        float4 v[8];
        #pragma unroll
        for (int u = 0; u < 8; u++)            // 8 independent 16B loads/lane
            v[u] = reinterpret_cast<const float4*>(row + c + u * 128)[lane];

        #pragma unroll
        for (int u = 0; u < 8; u++) {
            float m[4] = {v[u].x, v[u].y, v[u].z, v[u].w};
            #pragma unroll
            for (int k = 0; k < 4; k++) {
                unsigned bal = __ballot_sync(0xffffffffu, m[k] != 0.0f);
                if (m[k] != 0.0f) {
                    int pos = cnt + __popc(bal & ((1u << lane) - 1u));
                    if (pos < MAXNNZ)
                        g_idxT[pos][warp] =
                            (unsigned short)(c + u * 128 + lane * 4 + k);
                }
                cnt += __popc(bal);
            }
        }
    }
    if (lane == 0) g_cnt[warp] = cnt < MAXNNZ ? cnt : MAXNNZ;
}

// ---------------------------------------------------------------------------
// Kernel 2: block = one batch b x 512 consecutive check nodes.
//  - x row (8KB) staged into shared, coalesced: divergent gathers become LDS
//    (crossbar handles divergence) instead of 32-wavefront L1tex replays.
//  - index reads coalesced via transposed table.
//  - first 8 indices prefetched before the barrier to overlap latency.
//  - output store fully coalesced.
// ---------------------------------------------------------------------------
__global__ void __launch_bounds__(512)
check_node_update(const float* __restrict__ x, float* __restrict__ out) {
    __shared__ float s_x[IN_DIM];

    const int tid = threadIdx.x;                 // 0..511
    const int b   = blockIdx.y;                  // 0..127
    const int o   = blockIdx.x * 512 + tid;      // consecutive across warp

    // Stage x row: 512 threads x 1 float4 = 8KB, fully coalesced.
    const float4 stage =
        reinterpret_cast<const float4*>(x + (size_t)b * IN_DIM)[tid];

    // Prefetch count + first index chunk while the stage is in flight.
    const int n = g_cnt[o];
    unsigned short i0[8];
    #pragma unroll
    for (int k = 0; k < 8; k++)
        i0[k] = g_idxT[k][o];                    // coalesced 64B per warp

    reinterpret_cast<float4*>(s_x)[tid] = stage;
    __syncthreads();

    // Chunk 0 (covers ~60% of rows entirely, ~96% with chunk 1).
    float p;
    {
        float v[8];
        #pragma unroll
        for (int k = 0; k < 8; k++)
            v[k] = (k < n) ? s_x[i0[k] & (IN_DIM - 1)] : 1.0f;
        p = ((v[0] * v[1]) * (v[2] * v[3])) * ((v[4] * v[5]) * (v[6] * v[7]));
    }
    // Remaining chunks (rare).
    #pragma unroll 1
    for (int j0 = 8; j0 < n; j0 += 8) {
        float v[8];
        #pragma unroll
        for (int k = 0; k < 8; k++) {
            unsigned short idx = g_idxT[j0 + k][o];
            v[k] = (j0 + k < n) ? s_x[idx & (IN_DIM - 1)] : 1.0f;
        }
        p *= ((v[0] * v[1]) * (v[2] * v[3])) * ((v[4] * v[5]) * (v[6] * v[7]));
    }

    const float lim = 1.0f - 1e-7f;              // folds to 0.99999988f
    p = fminf(fmaxf(p, -lim), lim);

    out[(size_t)b * OUT_DIM + o] = logf((1.0f + p) / (1.0f - p));
}

// ---------------------------------------------------------------------------
extern "C" void kernel_launch(void* const* d_in, const int* in_sizes, int n_in,
                              void* d_out, int out_size) {
    const float* x    = (const float*)d_in[0];   // [128, 2048]
    const float* mask = (const float*)d_in[1];   // [1024, 2048]
    float*       out  = (float*)d_out;           // [128, 1024]

    build_row_indices<<<128, 256>>>(mask);       // 1024 warps, one per row

    dim3 grd(OUT_DIM / 512, BATCH);              // (2, 128) = 256 blocks
    check_node_update<<<grd, 512>>>(x, out);
}